// round 11
// baseline (speedup 1.0000x reference)
#include <cuda_runtime.h>

// Problem constants
#define PB 4
#define PN 8192
#define NPOINT 2048
#define PC 64
#define NS 32
#define SLOTS 33               // 1 (fps) + 32 samples
#define R2 (0.1f * 0.1f)
#define TPG (NPOINT * SLOTS)   // pairs per batch = 67584

#define GRID 10
#define NC (GRID * GRID * GRID)   // 1000 cells per batch

// Scratch (device globals; no allocation allowed)
__device__ float4 g_ft4[PB * PN * 16];          // 8 MB, features transposed (B, N, C)
__device__ int    g_cellstart[PB][NC + 1];
__device__ float4 g_pts[PB * PN];               // cell-sorted coords, idx in .w

__device__ __forceinline__ int cell_of(float x) {
    int c = (int)(x * 10.0f);
    return min(max(c, 0), GRID - 1);
}

// ---------------------------------------------------------------------------
// Kernel 0: transpose features (B, C, N) -> (B, N, C), all-128-bit pipeline.
// ---------------------------------------------------------------------------
__global__ __launch_bounds__(256) void transpose_kernel(const float* __restrict__ feat) {
    __shared__ float4 t4[64 * 16];   // 16 KB, swizzled: [n][cg ^ ((n>>2)&15)]

    int b  = blockIdx.y;
    int n0 = blockIdx.x * 64;
    int tid = threadIdx.x;
    int g = tid >> 4;    // c-group 0..15 (channels 4g..4g+3)
    int q = tid & 15;    // n-chunk  0..15

    const float4* fb4 = (const float4*)(feat + (size_t)b * PC * PN);
    float4 f[4];
#pragma unroll
    for (int p = 0; p < 4; p++)
        f[p] = fb4[(size_t)(4 * g + p) * (PN / 4) + (n0 >> 2) + q];

    {
        float4 v;
        v = make_float4(f[0].x, f[1].x, f[2].x, f[3].x);
        t4[(4 * q + 0) * 16 + (g ^ q)] = v;
        v = make_float4(f[0].y, f[1].y, f[2].y, f[3].y);
        t4[(4 * q + 1) * 16 + (g ^ q)] = v;
        v = make_float4(f[0].z, f[1].z, f[2].z, f[3].z);
        t4[(4 * q + 2) * 16 + (g ^ q)] = v;
        v = make_float4(f[0].w, f[1].w, f[2].w, f[3].w);
        t4[(4 * q + 3) * 16 + (g ^ q)] = v;
    }
    __syncthreads();

    float4* ob4 = g_ft4 + ((size_t)b * PN + n0) * 16;
#pragma unroll
    for (int k = 0; k < 4; k++) {
        int idx = k * 256 + tid;
        int n  = idx >> 4;
        int cg = idx & 15;
        ob4[n * 16 + cg] = t4[n * 16 + (cg ^ ((n >> 2) & 15))];
    }
}

// ---------------------------------------------------------------------------
// Kernel 1: fused grid build. One block per batch, vectorized point reads.
// ---------------------------------------------------------------------------
__global__ __launch_bounds__(1024) void grid_build_kernel(const float* __restrict__ xyz) {
    __shared__ int hist[NC];
    __shared__ int wsum[32];

    int b = blockIdx.x, t = threadIdx.x;
    int lane = t & 31, w = t >> 5;

    for (int i = t; i < NC; i += 1024) hist[i] = 0;
    __syncthreads();

    const float4* xb4 = (const float4*)(xyz + (size_t)b * PN * 3);
    float4 r4[6];
#pragma unroll
    for (int k = 0; k < 6; k++) r4[k] = xb4[t * 6 + k];
    const float* fp = (const float*)r4;

    int pc[8];
#pragma unroll
    for (int k = 0; k < 8; k++) {
        pc[k] = (cell_of(fp[3 * k + 2]) * GRID + cell_of(fp[3 * k + 1])) * GRID
                + cell_of(fp[3 * k + 0]);
        atomicAdd(&hist[pc[k]], 1);
    }
    __syncthreads();

    int v = (t < NC) ? hist[t] : 0;
    int s = v;
#pragma unroll
    for (int off = 1; off < 32; off <<= 1) {
        int u = __shfl_up_sync(0xFFFFFFFFu, s, off);
        if (lane >= off) s += u;
    }
    if (lane == 31) wsum[w] = s;
    __syncthreads();
    if (w == 0) {
        int ws = wsum[lane];
#pragma unroll
        for (int off = 1; off < 32; off <<= 1) {
            int u = __shfl_up_sync(0xFFFFFFFFu, ws, off);
            if (lane >= off) ws += u;
        }
        wsum[lane] = ws;
    }
    __syncthreads();
    int incl = s + (w > 0 ? wsum[w - 1] : 0);
    int excl = incl - v;
    __syncthreads();
    if (t < NC) {
        g_cellstart[b][t + 1] = incl;
        if (t == 0) g_cellstart[b][0] = 0;
        hist[t] = excl;
    }
    __syncthreads();

    float4* pout = g_pts + ((size_t)b << 13);
#pragma unroll
    for (int k = 0; k < 8; k++) {
        int pos = atomicAdd(&hist[pc[k]], 1);
        pout[pos] = make_float4(fp[3 * k + 0], fp[3 * k + 1], fp[3 * k + 2],
                                __int_as_float(t * 8 + k));
    }
}

// ---------------------------------------------------------------------------
// Warp bitonic sort of NR*32 ints (ascending), lane-major layout j = k*32+lane.
// ---------------------------------------------------------------------------
template <int NR>
__device__ __forceinline__ void bsort(int* r, int lane) {
    const int TOT = NR * 32;
#pragma unroll
    for (int size = 2; size <= TOT; size <<= 1) {
#pragma unroll
        for (int stride = size >> 1; stride > 0; stride >>= 1) {
            if (stride >= 32) {
                int ks = stride >> 5;
#pragma unroll
                for (int k = 0; k < NR; k++) {
                    if ((k & ks) == 0) {
                        int j = k * 32 + lane;
                        bool desc = (j & size) != 0;
                        int a = r[k], c = r[k + ks];
                        int lo = min(a, c), hi = max(a, c);
                        r[k]      = desc ? hi : lo;
                        r[k + ks] = desc ? lo : hi;
                    }
                }
            } else {
#pragma unroll
                for (int k = 0; k < NR; k++) {
                    int j = k * 32 + lane;
                    bool desc  = (j & size) != 0;
                    int  p     = __shfl_xor_sync(0xFFFFFFFFu, r[k], stride);
                    bool lower = (lane & stride) == 0;
                    r[k] = (lower != desc) ? min(r[k], p) : max(r[k], p);
                }
            }
        }
    }
}

// ---------------------------------------------------------------------------
// Kernel 2: FUSED ball query + gather + center + concat.
// One warp = one centroid: grid query -> sort -> write centered xyz channels
// (0-5) -> two 32-channel feature half-passes through a per-warp smem tile.
// Output (B, 70, NPOINT, 33).
// ---------------------------------------------------------------------------
#define FW 4   // warps (centroids) per block

__global__ __launch_bounds__(FW * 32) void bq_gather_kernel(
    const float* __restrict__ xyz, const float* __restrict__ new_xyz,
    const int* __restrict__ fps_idx, float* __restrict__ out) {
    __shared__ int   slots_[FW][128];
    __shared__ int   idxs[FW][34];
    __shared__ float stage[FW][32][34];   // [warp][channel][slot]

    int tid  = threadIdx.x;
    int w    = tid >> 5;
    int lane = tid & 31;
    int gc   = blockIdx.x * FW + w;       // centroid id in [0, B*NPOINT)
    int b    = gc / NPOINT;
    int j    = gc - b * NPOINT;

    float cx = new_xyz[gc * 3 + 0];
    float cy = new_xyz[gc * 3 + 1];
    float cz = new_xyz[gc * 3 + 2];
    int fpsv = fps_idx[gc];

    // ---- Phase 1: grid ball query (identical arithmetic to passing version)
    int icx = cell_of(cx), icy = cell_of(cy), icz = cell_of(cz);
    int xlo = max(icx - 1, 0), xhi = min(icx + 1, GRID - 1);
    int ylo = max(icy - 1, 0), yhi = min(icy + 1, GRID - 1);
    int zlo = max(icz - 1, 0), zhi = min(icz + 1, GRID - 1);
    int ny_ = yhi - ylo + 1;
    int nrows = (zhi - zlo + 1) * ny_;

    const int*    cs  = g_cellstart[b];
    const float4* pts = g_pts + ((size_t)b << 13);

    int rs_ = 0, re_ = 0;
    if (lane < nrows) {
        int z = zlo + lane / ny_;
        int y = ylo + lane % ny_;
        int rb = (z * GRID + y) * GRID;
        rs_ = __ldg(&cs[rb + xlo]);
        re_ = __ldg(&cs[rb + xhi + 1]);
    }

    int cnt = 0;
    for (int rr = 0; rr < nrows; rr++) {
        int s = __shfl_sync(0xFFFFFFFFu, rs_, rr);
        int e = __shfl_sync(0xFFFFFFFFu, re_, rr);
        for (int base = s; base < e; base += 32) {
            int  i   = base + lane;
            float4 p = pts[min(i, PN - 1)];
            float dx = cx - p.x, dy = cy - p.y, dz = cz - p.z;
            // Match XLA's unfused left-to-right sum exactly (no FMA):
            float d2 = __fadd_rn(__fadd_rn(__fmul_rn(dx, dx), __fmul_rn(dy, dy)),
                                 __fmul_rn(dz, dz));
            bool valid = (i < e) && (d2 < R2);
            unsigned m = __ballot_sync(0xFFFFFFFFu, valid);
            if (valid) {
                int pos = cnt + __popc(m & ((1u << lane) - 1u));
                if (pos < 128) slots_[w][pos] = __float_as_int(p.w);
            }
            cnt += __popc(m);
        }
    }
    __syncwarp();

    int cl = min(cnt, 128);
    int r[4];
#pragma unroll
    for (int k = 0; k < 4; k++) {
        int jj = k * 32 + lane;
        r[k] = (jj < cl) ? slots_[w][jj] : 0x7FFFFFFF;
    }
    if (cnt <= 32)      bsort<1>(r, lane);
    else if (cnt <= 64) bsort<2>(r, lane);
    else                bsort<4>(r, lane);

    int first = __shfl_sync(0xFFFFFFFFu, r[0], 0);
    int pad   = (cnt > 0) ? first : 0;
    int v     = (lane < cnt) ? r[0] : pad;

    if (lane == 0) idxs[w][0] = fpsv;
    idxs[w][1 + lane] = v;
    __syncwarp();

    // ---- Phase 2: centered xyz channels (0-2 and duplicated 3-5)
    const float* xb   = xyz + (size_t)b * PN * 3;
    float*       outb = out + (size_t)b * 70 * TPG + (size_t)j * SLOTS;
    {
        int   iv = idxs[w][lane];          // slot = lane (0..31)
        float dx = xb[iv * 3 + 0] - cx;
        float dy = xb[iv * 3 + 1] - cy;
        float dz = xb[iv * 3 + 2] - cz;
        outb[0 * (size_t)TPG + lane] = dx;
        outb[1 * (size_t)TPG + lane] = dy;
        outb[2 * (size_t)TPG + lane] = dz;
        outb[3 * (size_t)TPG + lane] = dx;
        outb[4 * (size_t)TPG + lane] = dy;
        outb[5 * (size_t)TPG + lane] = dz;
        if (lane == 0) {                   // slot 32
            int   iv2 = idxs[w][32];
            float ex = xb[iv2 * 3 + 0] - cx;
            float ey = xb[iv2 * 3 + 1] - cy;
            float ez = xb[iv2 * 3 + 2] - cz;
            outb[0 * (size_t)TPG + 32] = ex;
            outb[1 * (size_t)TPG + 32] = ey;
            outb[2 * (size_t)TPG + 32] = ez;
            outb[3 * (size_t)TPG + 32] = ex;
            outb[4 * (size_t)TPG + 32] = ey;
            outb[5 * (size_t)TPG + 32] = ez;
        }
    }

    // ---- Phase 3: feature channels (6..69), two 32-channel half-passes.
    // Lane = (sl, q8): sl = slot-within-group (0..3), q8 = float4 chunk (0..7).
    const float4* ftb4 = g_ft4 + (size_t)b * PN * 16;
    int sl = lane >> 3;
    int q8 = lane & 7;
#pragma unroll
    for (int h = 0; h < 2; h++) {
        __syncwarp();
#pragma unroll
        for (int sg = 0; sg < 9; sg++) {
            int slot = sg * 4 + sl;
            if (slot < SLOTS) {
                float4 f = ftb4[(size_t)idxs[w][slot] * 16 + h * 8 + q8];
                stage[w][q8 * 4 + 0][slot] = f.x;
                stage[w][q8 * 4 + 1][slot] = f.y;
                stage[w][q8 * 4 + 2][slot] = f.z;
                stage[w][q8 * 4 + 3][slot] = f.w;
            }
        }
        __syncwarp();
        float* oc = outb + (size_t)(6 + h * 32) * TPG;
#pragma unroll
        for (int c0 = 0; c0 < 32; c0++) {
            oc[(size_t)c0 * TPG + lane] = stage[w][c0][lane];
            if (lane == 0)
                oc[(size_t)c0 * TPG + 32] = stage[w][c0][32];
        }
    }
}

// ---------------------------------------------------------------------------
extern "C" void kernel_launch(void* const* d_in, const int* in_sizes, int n_in,
                              void* d_out, int out_size) {
    const float* xyz      = (const float*)d_in[0];   // (B, N, 3)
    const float* new_xyz  = (const float*)d_in[1];   // (B, NPOINT, 3)
    const float* features = (const float*)d_in[2];   // (B, C, N)
    const int*   fps_idx  = (const int*)d_in[3];     // (B, NPOINT)
    float* out = (float*)d_out;                      // (B, 70, NPOINT, 33)

    transpose_kernel<<<dim3(PN / 64, PB), 256>>>(features);
    grid_build_kernel<<<PB, 1024>>>(xyz);
    bq_gather_kernel<<<(PB * NPOINT) / FW, FW * 32>>>(xyz, new_xyz, fps_idx, out);
}

// round 12
// speedup vs baseline: 1.0562x; 1.0562x over previous
#include <cuda_runtime.h>

// Problem constants
#define PB 4
#define PN 8192
#define NPOINT 2048
#define PC 64
#define NS 32
#define SLOTS 33               // 1 (fps) + 32 samples
#define R2 (0.1f * 0.1f)
#define TPG (NPOINT * SLOTS)   // pairs per batch = 67584

#define GRID 10
#define NC (GRID * GRID * GRID)   // 1000 cells per batch

// Scratch (device globals; no allocation allowed)
__device__ int    g_idx[PB * NPOINT * SLOTS];   // 1.08 MB
__device__ float4 g_ft4[PB * PN * 16];          // 8 MB, features transposed (B, N, C)
__device__ int    g_cellstart[PB][NC + 1];
__device__ float4 g_pts[PB * PN];               // cell-sorted coords, idx in .w

__device__ __forceinline__ int cell_of(float x) {
    int c = (int)(x * 10.0f);
    return min(max(c, 0), GRID - 1);
}

// ---------------------------------------------------------------------------
// Kernel 0: transpose features (B, C, N) -> (B, N, C), all-128-bit pipeline.
// ---------------------------------------------------------------------------
__global__ __launch_bounds__(256) void transpose_kernel(const float* __restrict__ feat) {
    __shared__ float4 t4[64 * 16];   // 16 KB, swizzled: [n][cg ^ ((n>>2)&15)]

    int b  = blockIdx.y;
    int n0 = blockIdx.x * 64;
    int tid = threadIdx.x;
    int g = tid >> 4;    // c-group 0..15 (channels 4g..4g+3)
    int q = tid & 15;    // n-chunk  0..15

    const float4* fb4 = (const float4*)(feat + (size_t)b * PC * PN);
    float4 f[4];
#pragma unroll
    for (int p = 0; p < 4; p++)
        f[p] = fb4[(size_t)(4 * g + p) * (PN / 4) + (n0 >> 2) + q];

    {
        float4 v;
        v = make_float4(f[0].x, f[1].x, f[2].x, f[3].x);
        t4[(4 * q + 0) * 16 + (g ^ q)] = v;
        v = make_float4(f[0].y, f[1].y, f[2].y, f[3].y);
        t4[(4 * q + 1) * 16 + (g ^ q)] = v;
        v = make_float4(f[0].z, f[1].z, f[2].z, f[3].z);
        t4[(4 * q + 2) * 16 + (g ^ q)] = v;
        v = make_float4(f[0].w, f[1].w, f[2].w, f[3].w);
        t4[(4 * q + 3) * 16 + (g ^ q)] = v;
    }
    __syncthreads();

    float4* ob4 = g_ft4 + ((size_t)b * PN + n0) * 16;
#pragma unroll
    for (int k = 0; k < 4; k++) {
        int idx = k * 256 + tid;
        int n  = idx >> 4;
        int cg = idx & 15;
        ob4[n * 16 + cg] = t4[n * 16 + (cg ^ ((n >> 2) & 15))];
    }
}

// ---------------------------------------------------------------------------
// Kernel 1: fused grid build. One block per batch, vectorized point reads.
// ---------------------------------------------------------------------------
__global__ __launch_bounds__(1024) void grid_build_kernel(const float* __restrict__ xyz) {
    __shared__ int hist[NC];
    __shared__ int wsum[32];

    int b = blockIdx.x, t = threadIdx.x;
    int lane = t & 31, w = t >> 5;

    for (int i = t; i < NC; i += 1024) hist[i] = 0;
    __syncthreads();

    const float4* xb4 = (const float4*)(xyz + (size_t)b * PN * 3);
    float4 r4[6];
#pragma unroll
    for (int k = 0; k < 6; k++) r4[k] = xb4[t * 6 + k];
    const float* fp = (const float*)r4;

    int pc[8];
#pragma unroll
    for (int k = 0; k < 8; k++) {
        pc[k] = (cell_of(fp[3 * k + 2]) * GRID + cell_of(fp[3 * k + 1])) * GRID
                + cell_of(fp[3 * k + 0]);
        atomicAdd(&hist[pc[k]], 1);
    }
    __syncthreads();

    int v = (t < NC) ? hist[t] : 0;
    int s = v;
#pragma unroll
    for (int off = 1; off < 32; off <<= 1) {
        int u = __shfl_up_sync(0xFFFFFFFFu, s, off);
        if (lane >= off) s += u;
    }
    if (lane == 31) wsum[w] = s;
    __syncthreads();
    if (w == 0) {
        int ws = wsum[lane];
#pragma unroll
        for (int off = 1; off < 32; off <<= 1) {
            int u = __shfl_up_sync(0xFFFFFFFFu, ws, off);
            if (lane >= off) ws += u;
        }
        wsum[lane] = ws;
    }
    __syncthreads();
    int incl = s + (w > 0 ? wsum[w - 1] : 0);
    int excl = incl - v;
    __syncthreads();
    if (t < NC) {
        g_cellstart[b][t + 1] = incl;
        if (t == 0) g_cellstart[b][0] = 0;
        hist[t] = excl;
    }
    __syncthreads();

    float4* pout = g_pts + ((size_t)b << 13);
#pragma unroll
    for (int k = 0; k < 8; k++) {
        int pos = atomicAdd(&hist[pc[k]], 1);
        pout[pos] = make_float4(fp[3 * k + 0], fp[3 * k + 1], fp[3 * k + 2],
                                __int_as_float(t * 8 + k));
    }
}

// ---------------------------------------------------------------------------
// Warp bitonic sort of NR*32 ints (ascending), lane-major layout j = k*32+lane.
// ---------------------------------------------------------------------------
template <int NR>
__device__ __forceinline__ void bsort(int* r, int lane) {
    const int TOT = NR * 32;
#pragma unroll
    for (int size = 2; size <= TOT; size <<= 1) {
#pragma unroll
        for (int stride = size >> 1; stride > 0; stride >>= 1) {
            if (stride >= 32) {
                int ks = stride >> 5;
#pragma unroll
                for (int k = 0; k < NR; k++) {
                    if ((k & ks) == 0) {
                        int j = k * 32 + lane;
                        bool desc = (j & size) != 0;
                        int a = r[k], c = r[k + ks];
                        int lo = min(a, c), hi = max(a, c);
                        r[k]      = desc ? hi : lo;
                        r[k + ks] = desc ? lo : hi;
                    }
                }
            } else {
#pragma unroll
                for (int k = 0; k < NR; k++) {
                    int j = k * 32 + lane;
                    bool desc  = (j & size) != 0;
                    int  p     = __shfl_xor_sync(0xFFFFFFFFu, r[k], stride);
                    bool lower = (lane & stride) == 0;
                    r[k] = (lower != desc) ? min(r[k], p) : max(r[k], p);
                }
            }
        }
    }
}

// ---------------------------------------------------------------------------
// Kernel 2: grid ball query. One warp per centroid, parallel row-range preload.
// ---------------------------------------------------------------------------
#define BQ_WARPS 8

__global__ __launch_bounds__(BQ_WARPS * 32) void ballquery_grid_kernel(
    const float* __restrict__ new_xyz, const int* __restrict__ fps_idx) {
    __shared__ int slots[BQ_WARPS][128];

    int tid  = threadIdx.x;
    int w    = tid >> 5;
    int lane = tid & 31;
    int gc   = blockIdx.x * BQ_WARPS + w;
    int b    = gc / NPOINT;

    float cx = new_xyz[gc * 3 + 0];
    float cy = new_xyz[gc * 3 + 1];
    float cz = new_xyz[gc * 3 + 2];
    int fpsv = fps_idx[gc];

    int icx = cell_of(cx), icy = cell_of(cy), icz = cell_of(cz);
    int xlo = max(icx - 1, 0), xhi = min(icx + 1, GRID - 1);
    int ylo = max(icy - 1, 0), yhi = min(icy + 1, GRID - 1);
    int zlo = max(icz - 1, 0), zhi = min(icz + 1, GRID - 1);
    int ny_ = yhi - ylo + 1;
    int nrows = (zhi - zlo + 1) * ny_;

    const int*    cs  = g_cellstart[b];
    const float4* pts = g_pts + ((size_t)b << 13);

    int rs_ = 0, re_ = 0;
    if (lane < nrows) {
        int z = zlo + lane / ny_;
        int y = ylo + lane % ny_;
        int rb = (z * GRID + y) * GRID;
        rs_ = __ldg(&cs[rb + xlo]);
        re_ = __ldg(&cs[rb + xhi + 1]);
    }

    int cnt = 0;
    for (int rr = 0; rr < nrows; rr++) {
        int s = __shfl_sync(0xFFFFFFFFu, rs_, rr);
        int e = __shfl_sync(0xFFFFFFFFu, re_, rr);
        for (int base = s; base < e; base += 32) {
            int  i   = base + lane;
            float4 p = pts[min(i, PN - 1)];
            float dx = cx - p.x, dy = cy - p.y, dz = cz - p.z;
            // Match XLA's unfused left-to-right sum exactly (no FMA):
            float d2 = __fadd_rn(__fadd_rn(__fmul_rn(dx, dx), __fmul_rn(dy, dy)),
                                 __fmul_rn(dz, dz));
            bool valid = (i < e) && (d2 < R2);
            unsigned m = __ballot_sync(0xFFFFFFFFu, valid);
            if (valid) {
                int pos = cnt + __popc(m & ((1u << lane) - 1u));
                if (pos < 128) slots[w][pos] = __float_as_int(p.w);
            }
            cnt += __popc(m);
        }
    }
    __syncwarp();

    int cl = min(cnt, 128);
    int r[4];
#pragma unroll
    for (int k = 0; k < 4; k++) {
        int j = k * 32 + lane;
        r[k] = (j < cl) ? slots[w][j] : 0x7FFFFFFF;
    }
    if (cnt <= 32)      bsort<1>(r, lane);
    else if (cnt <= 64) bsort<2>(r, lane);
    else                bsort<4>(r, lane);

    int first = __shfl_sync(0xFFFFFFFFu, r[0], 0);
    int pad   = (cnt > 0) ? first : 0;
    int v     = (lane < cnt) ? r[0] : pad;

    int base = gc * SLOTS;
    if (lane == 0) g_idx[base] = fpsv;
    g_idx[base + 1 + lane] = v;
}

// ---------------------------------------------------------------------------
// Kernel 3: gather + center + concat, software-pipelined multi-tile blocks.
// 256 threads, NT=4 tiles of 64 pairs; one head phase for all 256 pairs;
// double-buffered stage/emit: LDG(t+1) issued before barrier so its latency
// hides behind emit(t). Proven GP=64 swizzle. Output (B, 70, NPOINT, 33).
// ---------------------------------------------------------------------------
#define GP 64
#define NT 4
#define PAIRS (GP * NT)          // 256 pairs per block
#define GBPB (TPG / PAIRS)       // 264 blocks per batch

__global__ __launch_bounds__(256) void gather_kernel(
    const float* __restrict__ xyz, const float* __restrict__ new_xyz,
    float* __restrict__ out) {
    __shared__ float4 buf[2][PC * 16];      // 2 x 16 KB, swizzled [c][g ^ ((c>>2)&15)]
    __shared__ float4 cent4[3][PAIRS / 4];  // 3 KB
    __shared__ int    sidx[PAIRS];          // 1 KB

    int bb  = blockIdx.x / GBPB;
    int T0  = (blockIdx.x % GBPB) * PAIRS;  // global pair offset within batch
    int tid = threadIdx.x;

    // ---- Head: all 256 pairs at once (256 idx loads in flight).
    {
        int t = T0 + tid;
        int j = t / SLOTS;
        int s = t - j * SLOTS;
        int iv = g_idx[(bb * NPOINT + j) * SLOTS + s];
        sidx[tid] = iv;
        const float* nz = new_xyz + ((size_t)bb * NPOINT + j) * 3;
        const float* pz = xyz + ((size_t)bb * PN + iv) * 3;
        ((float*)&cent4[0][0])[tid] = pz[0] - nz[0];
        ((float*)&cent4[1][0])[tid] = pz[1] - nz[1];
        ((float*)&cent4[2][0])[tid] = pz[2] - nz[2];
    }
    __syncthreads();

    const float4* ftb4 = g_ft4 + (size_t)bb * PN * 16;
    int g = tid >> 4;   // pair-group 0..15 within tile
    int q = tid & 15;   // chunk 0..15

    // Prefetch tile 0.
    float4 f[4];
#pragma unroll
    for (int p = 0; p < 4; p++)
        f[p] = ftb4[(size_t)sidx[4 * g + p] * 16 + q];

    float* ob_base = out + (size_t)bb * 70 * TPG + T0;

#pragma unroll
    for (int t = 0; t < NT; t++) {
        float4* bt = buf[t & 1];
        // STS current tile (4x4 register transpose, swizzled).
        {
            float4 v;
            v = make_float4(f[0].x, f[1].x, f[2].x, f[3].x);
            bt[(4 * q + 0) * 16 + (g ^ q)] = v;
            v = make_float4(f[0].y, f[1].y, f[2].y, f[3].y);
            bt[(4 * q + 1) * 16 + (g ^ q)] = v;
            v = make_float4(f[0].z, f[1].z, f[2].z, f[3].z);
            bt[(4 * q + 2) * 16 + (g ^ q)] = v;
            v = make_float4(f[0].w, f[1].w, f[2].w, f[3].w);
            bt[(4 * q + 3) * 16 + (g ^ q)] = v;
        }
        // Prefetch next tile BEFORE the barrier: latency hides behind emit(t).
        if (t + 1 < NT) {
            const int* sx = sidx + (t + 1) * GP;
#pragma unroll
            for (int p = 0; p < 4; p++)
                f[p] = ftb4[(size_t)sx[4 * g + p] * 16 + q];
        }
        __syncthreads();

        // Emit tile t: 70 channels x 16 float4-groups, LDS.128 + STG.128.
        float* ob = ob_base + t * GP;
        for (int k = tid; k < 70 * 16; k += 256) {
            int c  = k >> 4;
            int gg = k & 15;
            float4 v;
            if (c < 6) {
                v = cent4[c < 3 ? c : c - 3][t * 16 + gg];
            } else {
                int cf = c - 6;
                v = bt[cf * 16 + (gg ^ ((cf >> 2) & 15))];
            }
            *(float4*)(ob + (size_t)c * TPG + 4 * gg) = v;
        }
        // No second barrier needed: next STS targets the other buffer, and the
        // next iteration's barrier orders emit(t) before STS(t+2) reuses bt.
    }
}

// ---------------------------------------------------------------------------
extern "C" void kernel_launch(void* const* d_in, const int* in_sizes, int n_in,
                              void* d_out, int out_size) {
    const float* xyz      = (const float*)d_in[0];   // (B, N, 3)
    const float* new_xyz  = (const float*)d_in[1];   // (B, NPOINT, 3)
    const float* features = (const float*)d_in[2];   // (B, C, N)
    const int*   fps_idx  = (const int*)d_in[3];     // (B, NPOINT)
    float* out = (float*)d_out;                      // (B, 70, NPOINT, 33)

    transpose_kernel<<<dim3(PN / 64, PB), 256>>>(features);
    grid_build_kernel<<<PB, 1024>>>(xyz);
    ballquery_grid_kernel<<<(PB * NPOINT) / BQ_WARPS, BQ_WARPS * 32>>>(new_xyz, fps_idx);
    gather_kernel<<<PB * GBPB, 256>>>(xyz, new_xyz, out);
}